// round 8
// baseline (speedup 1.0000x reference)
#include <cuda_runtime.h>
#include <cuda_bf16.h>
#include <cstdint>
#include <cstddef>

#define BB 2
#define TT 2048
#define DD 2048
#define HH 16
#define HDD 128
#define MROWS (BB*TT)   // 4096

// ---------------- scratch (static device globals; no runtime alloc) ----------------
__device__ float g_qkv[(size_t)BB * TT * 3 * DD];   // [B,T,3D]

// bf16 hi/lo splits
__device__ __nv_bfloat16 g_xhi[(size_t)MROWS * DD];
__device__ __nv_bfloat16 g_xlo[(size_t)MROWS * DD];
__device__ __nv_bfloat16 g_wqh[(size_t)3 * DD * DD];
__device__ __nv_bfloat16 g_wql[(size_t)3 * DD * DD];
__device__ __nv_bfloat16 g_woh[(size_t)DD * DD];
__device__ __nv_bfloat16 g_wol[(size_t)DD * DD];
__device__ __nv_bfloat16 g_ahi[(size_t)MROWS * DD];   // attn out (written by flash)
__device__ __nv_bfloat16 g_alo[(size_t)MROWS * DD];

// q/k/v hi-lo bf16, [B,H,T,HD]
#define QKVN ((size_t)BB * HH * TT * HDD)
__device__ __nv_bfloat16 g_qh[QKVN];
__device__ __nv_bfloat16 g_ql[QKVN];
__device__ __nv_bfloat16 g_kh[QKVN];
__device__ __nv_bfloat16 g_kl[QKVN];
__device__ __nv_bfloat16 g_vh[QKVN];
__device__ __nv_bfloat16 g_vl[QKVN];

// ---------------- PTX helpers (sm_80-era, safe on plain sm_100) ----------------
__device__ __forceinline__ uint32_t smem_u32(const void* p) {
    uint32_t a;
    asm("{ .reg .u64 t; cvta.to.shared.u64 t, %1; cvt.u32.u64 %0, t; }" : "=r"(a) : "l"(p));
    return a;
}
#define CP_ASYNC16(dst, src) \
    asm volatile("cp.async.cg.shared.global [%0], [%1], 16;" :: "r"(dst), "l"(src))
#define CP_COMMIT() asm volatile("cp.async.commit_group;" ::: "memory")
#define CP_WAIT0()  asm volatile("cp.async.wait_group 0;" ::: "memory")
#define CP_WAIT1()  asm volatile("cp.async.wait_group 1;" ::: "memory")

__device__ __forceinline__ void ldmx4(uint32_t* r, uint32_t addr) {
    asm volatile("ldmatrix.sync.aligned.m8n8.x4.shared.b16 {%0,%1,%2,%3}, [%4];"
                 : "=r"(r[0]), "=r"(r[1]), "=r"(r[2]), "=r"(r[3]) : "r"(addr));
}
__device__ __forceinline__ void ldmx4t(uint32_t* r, uint32_t addr) {
    asm volatile("ldmatrix.sync.aligned.m8n8.x4.trans.shared.b16 {%0,%1,%2,%3}, [%4];"
                 : "=r"(r[0]), "=r"(r[1]), "=r"(r[2]), "=r"(r[3]) : "r"(addr));
}
__device__ __forceinline__ void mma_bf16(float* d, const uint32_t* a, const uint32_t* b) {
    asm volatile(
        "mma.sync.aligned.m16n8k16.row.col.f32.bf16.bf16.f32 "
        "{%0,%1,%2,%3}, {%4,%5,%6,%7}, {%8,%9}, {%0,%1,%2,%3};"
        : "+f"(d[0]), "+f"(d[1]), "+f"(d[2]), "+f"(d[3])
        : "r"(a[0]), "r"(a[1]), "r"(a[2]), "r"(a[3]), "r"(b[0]), "r"(b[1]));
}
// pack fp32 pair (p0 -> low, p1 -> high) into bf16x2 hi part + residual lo part
__device__ __forceinline__ void pack_hilo(float p0, float p1, uint32_t& hp, uint32_t& lp) {
    asm("cvt.rn.bf16x2.f32 %0, %1, %2;" : "=r"(hp) : "f"(p1), "f"(p0));
    float h0 = __uint_as_float(hp << 16);
    float h1 = __uint_as_float(hp & 0xFFFF0000u);
    float l0 = p0 - h0, l1 = p1 - h1;
    asm("cvt.rn.bf16x2.f32 %0, %1, %2;" : "=r"(lp) : "f"(l1), "f"(l0));
}

// ---------------- fp32 -> bf16 hi/lo split ----------------
__global__ void split_bf16(const float* __restrict__ s,
                           __nv_bfloat16* __restrict__ hi,
                           __nv_bfloat16* __restrict__ lo, int n4)
{
    int i = blockIdx.x * 256 + threadIdx.x;
    if (i >= n4) return;
    float4 v = ((const float4*)s)[i];
    __nv_bfloat16 h0 = __float2bfloat16(v.x), h1 = __float2bfloat16(v.y);
    __nv_bfloat16 h2 = __float2bfloat16(v.z), h3 = __float2bfloat16(v.w);
    __nv_bfloat16 l0 = __float2bfloat16(v.x - __bfloat162float(h0));
    __nv_bfloat16 l1 = __float2bfloat16(v.y - __bfloat162float(h1));
    __nv_bfloat16 l2 = __float2bfloat16(v.z - __bfloat162float(h2));
    __nv_bfloat16 l3 = __float2bfloat16(v.w - __bfloat162float(h3));
    __nv_bfloat162* hp = (__nv_bfloat162*)hi;
    __nv_bfloat162* lp = (__nv_bfloat162*)lo;
    hp[2 * i]     = __nv_bfloat162(h0, h1);
    hp[2 * i + 1] = __nv_bfloat162(h2, h3);
    lp[2 * i]     = __nv_bfloat162(l0, l1);
    lp[2 * i + 1] = __nv_bfloat162(l2, l3);
}

// ---------------- mma.sync bf16-split GEMM: C[M,N] = A[M,K] @ B[N,K]^T ----------------
#define GK 32
#define SROWB 80
#define TBYTES (128 * SROWB)
#define GEMM_SMEM (8 * TBYTES)         // 81920

__global__ __launch_bounds__(256, 2) void gemm_bf16s(
    const __nv_bfloat16* __restrict__ Ah, const __nv_bfloat16* __restrict__ Al,
    const __nv_bfloat16* __restrict__ Bh, const __nv_bfloat16* __restrict__ Bl,
    float* __restrict__ C, int M, int N, int K)
{
    extern __shared__ char smg[];
    const uint32_t sb = smem_u32(smg);
    const int tid = threadIdx.x;
    const int wid = tid >> 5, lane = tid & 31;
    const int wm = wid >> 2, wn = wid & 3;
    const int brow = blockIdx.y * 128, bcol = blockIdx.x * 128;
    const int nch = K / GK;

    const __nv_bfloat16* srcs[4] = { Ah, Al, Bh, Bl };

    auto load_chunk = [&](int c) {
        const uint32_t base = sb + (uint32_t)(c & 1) * 4 * TBYTES;
        const size_t ka = (size_t)c * GK;
        #pragma unroll
        for (int t = 0; t < 4; t++) {
            const __nv_bfloat16* s = srcs[t];
            const int rowbase = (t < 2) ? brow : bcol;
            #pragma unroll
            for (int j = 0; j < 2; j++) {
                int i = tid * 2 + j;
                int r = i >> 2, ch = i & 3;
                const __nv_bfloat16* g = s + (size_t)(rowbase + r) * K + ka + ch * 8;
                CP_ASYNC16(base + t * TBYTES + r * SROWB + ch * 16, g);
            }
        }
        CP_COMMIT();
    };

    float acc[4][4][4];
    #pragma unroll
    for (int mt = 0; mt < 4; mt++)
        #pragma unroll
        for (int nt = 0; nt < 4; nt++)
            #pragma unroll
            for (int e = 0; e < 4; e++) acc[mt][nt][e] = 0.f;

    const uint32_t a_row = (uint32_t)(wm * 64 + (lane & 15)) * SROWB + (lane >> 4) * 16;
    const uint32_t b_row0 = (uint32_t)(wn * 32 + ((lane >> 4) & 1) * 8 + (lane & 7)) * SROWB
                            + ((lane >> 3) & 1) * 16;

    load_chunk(0);

    for (int c = 0; c < nch; c++) {
        if (c + 1 < nch) { load_chunk(c + 1); CP_WAIT1(); }
        else CP_WAIT0();
        __syncthreads();

        const uint32_t bufb = sb + (uint32_t)(c & 1) * 4 * TBYTES;
        #pragma unroll
        for (int ks = 0; ks < 2; ks++) {
            const uint32_t ko = ks * 32;
            uint32_t ah[4][4], al[4][4];
            #pragma unroll
            for (int mt = 0; mt < 4; mt++) {
                uint32_t addr = bufb + a_row + (uint32_t)(mt * 16) * SROWB + ko;
                ldmx4(ah[mt], addr);
                ldmx4(al[mt], addr + TBYTES);
            }
            uint32_t bh[4][2], bl[4][2];
            #pragma unroll
            for (int p = 0; p < 2; p++) {
                uint32_t addr = bufb + 2 * TBYTES + b_row0 + (uint32_t)(p * 16) * SROWB + ko;
                uint32_t rh[4], rl[4];
                ldmx4(rh, addr);
                ldmx4(rl, addr + TBYTES);
                bh[2*p][0] = rh[0]; bh[2*p][1] = rh[1];
                bh[2*p+1][0] = rh[2]; bh[2*p+1][1] = rh[3];
                bl[2*p][0] = rl[0]; bl[2*p][1] = rl[1];
                bl[2*p+1][0] = rl[2]; bl[2*p+1][1] = rl[3];
            }
            #pragma unroll
            for (int mt = 0; mt < 4; mt++)
                #pragma unroll
                for (int nt = 0; nt < 4; nt++) {
                    mma_bf16(acc[mt][nt], ah[mt], bh[nt]);
                    mma_bf16(acc[mt][nt], ah[mt], bl[nt]);
                    mma_bf16(acc[mt][nt], al[mt], bh[nt]);
                }
        }
        __syncthreads();
    }

    const int g = lane >> 2, t4 = lane & 3;
    #pragma unroll
    for (int mt = 0; mt < 4; mt++) {
        #pragma unroll
        for (int nt = 0; nt < 4; nt++) {
            int row = brow + wm * 64 + mt * 16 + g;
            int col = bcol + wn * 32 + nt * 8 + 2 * t4;
            float* p0 = C + (size_t)row * N + col;
            float* p1 = C + (size_t)(row + 8) * N + col;
            p0[0] = acc[mt][nt][0]; p0[1] = acc[mt][nt][1];
            p1[0] = acc[mt][nt][2]; p1[1] = acc[mt][nt][3];
        }
    }
}

// ---------------- RoPE + split into bf16 hi/lo [B,H,T,HD]; q pre-scaled ----------------
__global__ void rope_split(const float* __restrict__ qkv,
                           const float* __restrict__ cosT,
                           const float* __restrict__ sinT)
{
    const int idx = blockIdx.x;
    const int h = idx % HH;
    const int t = (idx / HH) % TT;
    const int b = idx / (HH * TT);
    const int c = threadIdx.x;

    const size_t ibase = ((size_t)(b * TT + t)) * (3 * DD) + h * HDD;
    float qv = qkv[ibase + c];
    float kv = qkv[ibase + DD + c];
    float vv = qkv[ibase + 2 * DD + c];
    float qp = qkv[ibase + (c ^ 64)];
    float kp = qkv[ibase + DD + (c ^ 64)];
    float cs = cosT[t * HDD + c];
    float sn = sinT[t * HDD + c];
    float sgn = (c < 64) ? -1.f : 1.f;

    float q = fmaf(qv, cs, sgn * qp * sn) * 0.08838834764831845f;  // fold 1/sqrt(128)
    float k = fmaf(kv, cs, sgn * kp * sn);

    const size_t o = (((size_t)(b * HH + h)) * TT + t) * HDD + c;
    __nv_bfloat16 qh = __float2bfloat16(q);
    __nv_bfloat16 kh = __float2bfloat16(k);
    __nv_bfloat16 vh = __float2bfloat16(vv);
    g_qh[o] = qh; g_ql[o] = __float2bfloat16(q - __bfloat162float(qh));
    g_kh[o] = kh; g_kl[o] = __float2bfloat16(k - __bfloat162float(kh));
    g_vh[o] = vh; g_vl[o] = __float2bfloat16(vv - __bfloat162float(vh));
}

// ---------------- tensor-core flash attention v3 ----------------
// 128x32 tiles; Q resident; K/V single-buffered (FK3=32); 2 CTAs/SM.
#define FQ2 128
#define FK3 32
#define FSTR 272                        // row stride bytes (128 bf16 + 16B pad)
#define SM_QH 0
#define SM_QL (FQ2*FSTR)                // 34816
#define SM_K  (2*FQ2*FSTR)              // 69632
#define HLOFF (FK3*FSTR)                // 8704 (hi->lo offset)
#define FLASH2_SMEM (SM_K + 4*HLOFF)    // 104448  (Khi,Klo,Vhi,Vlo)

__global__ __launch_bounds__(256, 2) void flash_mma()
{
    extern __shared__ char smf[];
    const uint32_t sb = smem_u32(smf);
    const int tid = threadIdx.x;
    const int wid = tid >> 5, lane = tid & 31;

    // longest-first static schedule: linear index -> (qt desc, h, b)
    const int l = blockIdx.x + 16 * blockIdx.y + 256 * blockIdx.z;   // 0..511
    const int qt = (TT / FQ2 - 1) - (l >> 5);                        // 15..0
    const int bh = l & 31;
    const int h = bh & 15, b = bh >> 4;

    const size_t hb = ((size_t)(b * HH + h)) * TT * HDD;
    const size_t qb = hb + (size_t)qt * FQ2 * HDD;

    const uint32_t kbase = sb + SM_K;
    const uint32_t vbase = sb + SM_K + 2 * HLOFF;

    auto load_kv = [&](int kt) {
        const size_t kb = hb + (size_t)kt * FK3 * HDD;
        #pragma unroll
        for (int j = 0; j < 2; j++) {
            int i = tid + j * 256;              // 0..511
            int r = i >> 4, ch = i & 15;        // 32 rows x 16 chunks
            size_t goff = kb + (size_t)r * HDD + ch * 8;
            uint32_t soff = (uint32_t)r * FSTR + ch * 16;
            CP_ASYNC16(kbase + soff, g_kh + goff);
            CP_ASYNC16(kbase + HLOFF + soff, g_kl + goff);
            CP_ASYNC16(vbase + soff, g_vh + goff);
            CP_ASYNC16(vbase + HLOFF + soff, g_vl + goff);
        }
        CP_COMMIT();
    };

    // ---- prologue: Q hi/lo via cp.async (resident) ----
    #pragma unroll
    for (int j = 0; j < 8; j++) {
        int i = tid + j * 256;                  // 0..2047
        int r = i >> 4, ch = i & 15;
        size_t goff = qb + (size_t)r * HDD + ch * 8;
        uint32_t soff = (uint32_t)r * FSTR + ch * 16;
        CP_ASYNC16(sb + SM_QH + soff, g_qh + goff);
        CP_ASYNC16(sb + SM_QL + soff, g_ql + goff);
    }
    CP_COMMIT();

    // fragment base addresses
    const uint32_t aq  = sb + SM_QH + (uint32_t)(wid * 16 + (lane & 15)) * FSTR + (lane >> 4) * 16;
    const uint32_t akr = (uint32_t)((lane & 7) + ((lane >> 4) << 3)) * FSTR + ((lane >> 3) & 1) * 16;
    const uint32_t avr = (uint32_t)((lane & 7) + ((lane >> 3) & 1) * 8) * FSTR + ((lane >> 4) << 3) * 2;

    float oacc[16][4];
    #pragma unroll
    for (int i = 0; i < 16; i++)
        #pragma unroll
        for (int e = 0; e < 4; e++) oacc[i][e] = 0.f;
    float mrow[2] = { -1e30f, -1e30f }, lrow[2] = { 0.f, 0.f };

    const int ktmax = 4 * qt + 3;
    for (int kt = 0; kt <= ktmax; kt++) {
        if (kt) __syncthreads();            // all warps done with K/V buffer
        load_kv(kt);
        CP_WAIT0();
        __syncthreads();

        // ---- S = Q @ K^T (scale folded into Q); N = 32 ----
        float sacc[4][4];
        #pragma unroll
        for (int nt = 0; nt < 4; nt++)
            #pragma unroll
            for (int e = 0; e < 4; e++) sacc[nt][e] = 0.f;

        #pragma unroll
        for (int ks = 0; ks < 8; ks++) {
            uint32_t qh4[4], ql4[4];
            ldmx4(qh4, aq + ks * 32);
            ldmx4(ql4, aq + (SM_QL - SM_QH) + ks * 32);
            #pragma unroll
            for (int p = 0; p < 2; p++) {
                uint32_t kh4[4], kl4[4];
                uint32_t kaddr = kbase + akr + (uint32_t)(p * 16) * FSTR + ks * 32;
                ldmx4(kh4, kaddr);
                ldmx4(kl4, kaddr + HLOFF);
                mma_bf16(sacc[2*p],   qh4, &kh4[0]);
                mma_bf16(sacc[2*p],   qh4, &kl4[0]);
                mma_bf16(sacc[2*p],   ql4, &kh4[0]);
                mma_bf16(sacc[2*p+1], qh4, &kh4[2]);
                mma_bf16(sacc[2*p+1], qh4, &kl4[2]);
                mma_bf16(sacc[2*p+1], ql4, &kh4[2]);
            }
        }

        // ---- causal mask (only diagonal-adjacent tiles: kt >= 4*qt) ----
        if (kt >= 4 * qt) {
            const int qrow0 = qt * FQ2 + wid * 16 + (lane >> 2);
            #pragma unroll
            for (int nt = 0; nt < 4; nt++) {
                int kc = kt * FK3 + nt * 8 + 2 * (lane & 3);
                if (kc     > qrow0)     sacc[nt][0] = -1e30f;
                if (kc + 1 > qrow0)     sacc[nt][1] = -1e30f;
                if (kc     > qrow0 + 8) sacc[nt][2] = -1e30f;
                if (kc + 1 > qrow0 + 8) sacc[nt][3] = -1e30f;
            }
        }

        // ---- online softmax (rows g, g+8; 4-lane groups share a row) ----
        #pragma unroll
        for (int r = 0; r < 2; r++) {
            float mt = fmaxf(fmaxf(sacc[0][2*r], sacc[0][2*r+1]),
                             fmaxf(sacc[1][2*r], sacc[1][2*r+1]));
            mt = fmaxf(mt, fmaxf(fmaxf(sacc[2][2*r], sacc[2][2*r+1]),
                                 fmaxf(sacc[3][2*r], sacc[3][2*r+1])));
            mt = fmaxf(mt, __shfl_xor_sync(0xffffffffu, mt, 1));
            mt = fmaxf(mt, __shfl_xor_sync(0xffffffffu, mt, 2));
            float mnew = fmaxf(mrow[r], mt);
            float alpha = __expf(mrow[r] - mnew);
            mrow[r] = mnew;
            float rs = 0.f;
            #pragma unroll
            for (int nt = 0; nt < 4; nt++) {
                float p0 = __expf(sacc[nt][2 * r]     - mnew);
                float p1 = __expf(sacc[nt][2 * r + 1] - mnew);
                sacc[nt][2 * r] = p0; sacc[nt][2 * r + 1] = p1;
                rs += p0 + p1;
            }
            rs += __shfl_xor_sync(0xffffffffu, rs, 1);
            rs += __shfl_xor_sync(0xffffffffu, rs, 2);
            lrow[r] = lrow[r] * alpha + rs;
            #pragma unroll
            for (int nt2 = 0; nt2 < 16; nt2++) {
                oacc[nt2][2 * r]     *= alpha;
                oacc[nt2][2 * r + 1] *= alpha;
            }
        }

        // ---- pack P into bf16 hi/lo A-fragments (2 k-steps of 16) ----
        uint32_t ph[2][4], pl[2][4];
        #pragma unroll
        for (int ks2 = 0; ks2 < 2; ks2++) {
            pack_hilo(sacc[2*ks2][0],   sacc[2*ks2][1],   ph[ks2][0], pl[ks2][0]);
            pack_hilo(sacc[2*ks2][2],   sacc[2*ks2][3],   ph[ks2][1], pl[ks2][1]);
            pack_hilo(sacc[2*ks2+1][0], sacc[2*ks2+1][1], ph[ks2][2], pl[ks2][2]);
            pack_hilo(sacc[2*ks2+1][2], sacc[2*ks2+1][3], ph[ks2][3], pl[ks2][3]);
        }

        // ---- O += P @ V (V fragments via ldmatrix.trans, row-major V) ----
        #pragma unroll
        for (int ks2 = 0; ks2 < 2; ks2++) {
            #pragma unroll
            for (int np = 0; np < 8; np++) {
                uint32_t vh4[4], vl4[4];
                uint32_t vaddr = vbase + avr + (uint32_t)(ks2 * 16) * FSTR + (np * 16) * 2;
                ldmx4t(vh4, vaddr);
                ldmx4t(vl4, vaddr + HLOFF);
                mma_bf16(oacc[2*np],   ph[ks2], &vh4[0]);
                mma_bf16(oacc[2*np],   ph[ks2], &vl4[0]);
                mma_bf16(oacc[2*np],   pl[ks2], &vh4[0]);
                mma_bf16(oacc[2*np+1], ph[ks2], &vh4[2]);
                mma_bf16(oacc[2*np+1], ph[ks2], &vl4[2]);
                mma_bf16(oacc[2*np+1], pl[ks2], &vh4[2]);
            }
        }
    }

    // ---- epilogue: normalize and write bf16 hi/lo out-proj input [B,T,D] ----
    const float inv0 = 1.f / lrow[0], inv1 = 1.f / lrow[1];
    const int row0 = qt * FQ2 + wid * 16 + (lane >> 2);
    #pragma unroll
    for (int nt2 = 0; nt2 < 16; nt2++) {
        int col = h * HDD + nt2 * 8 + 2 * (lane & 3);
        size_t i0 = (size_t)(b * TT + row0) * DD + col;
        size_t i1 = (size_t)(b * TT + row0 + 8) * DD + col;
        uint32_t hp, lp;
        pack_hilo(oacc[nt2][0] * inv0, oacc[nt2][1] * inv0, hp, lp);
        *(uint32_t*)&g_ahi[i0] = hp; *(uint32_t*)&g_alo[i0] = lp;
        pack_hilo(oacc[nt2][2] * inv1, oacc[nt2][3] * inv1, hp, lp);
        *(uint32_t*)&g_ahi[i1] = hp; *(uint32_t*)&g_alo[i1] = lp;
    }
}

// ---------------- launch ----------------
extern "C" void kernel_launch(void* const* d_in, const int* in_sizes, int n_in,
                              void* d_out, int out_size)
{
    const float* x    = (const float*)d_in[0];
    const float* cosT = (const float*)d_in[1];
    const float* sinT = (const float*)d_in[2];
    const float* Wqkv = (const float*)d_in[3];
    const float* Wout = (const float*)d_in[4];
    float* out = (float*)d_out;

    float* qkv_p;
    cudaGetSymbolAddress((void**)&qkv_p, g_qkv);
    __nv_bfloat16 *xhi, *xlo, *wqh, *wql, *woh, *wol, *ahi, *alo;
    cudaGetSymbolAddress((void**)&xhi, g_xhi);
    cudaGetSymbolAddress((void**)&xlo, g_xlo);
    cudaGetSymbolAddress((void**)&wqh, g_wqh);
    cudaGetSymbolAddress((void**)&wql, g_wql);
    cudaGetSymbolAddress((void**)&woh, g_woh);
    cudaGetSymbolAddress((void**)&wol, g_wol);
    cudaGetSymbolAddress((void**)&ahi, g_ahi);
    cudaGetSymbolAddress((void**)&alo, g_alo);

    cudaFuncSetAttribute(gemm_bf16s, cudaFuncAttributeMaxDynamicSharedMemorySize, GEMM_SMEM);
    cudaFuncSetAttribute(flash_mma, cudaFuncAttributeMaxDynamicSharedMemorySize, FLASH2_SMEM);

    // 0) bf16 hi/lo splits of x and weights
    split_bf16<<<(MROWS * DD / 4 + 255) / 256, 256>>>(x, xhi, xlo, MROWS * DD / 4);
    split_bf16<<<(3 * DD * DD / 4 + 255) / 256, 256>>>(Wqkv, wqh, wql, 3 * DD * DD / 4);
    split_bf16<<<(DD * DD / 4 + 255) / 256, 256>>>(Wout, woh, wol, DD * DD / 4);

    // 1) QKV projection (tensor cores)
    gemm_bf16s<<<dim3(3 * DD / 128, MROWS / 128), 256, GEMM_SMEM>>>(
        xhi, xlo, wqh, wql, qkv_p, MROWS, 3 * DD, DD);

    // 2) RoPE + bf16 hi/lo split of q,k,v
    rope_split<<<BB * TT * HH, HDD>>>(qkv_p, cosT, sinT);

    // 3) causal flash attention (tensor cores), writes g_ahi/g_alo
    flash_mma<<<dim3(TT / FQ2, HH, BB), 256, FLASH2_SMEM>>>();

    // 4) output projection (tensor cores)
    gemm_bf16s<<<dim3(DD / 128, MROWS / 128), 256, GEMM_SMEM>>>(
        ahi, alo, woh, wol, out, MROWS, DD, DD);
}

// round 10
// speedup vs baseline: 1.0442x; 1.0442x over previous
#include <cuda_runtime.h>
#include <cuda_bf16.h>
#include <cstdint>
#include <cstddef>

#define BB 2
#define TT 2048
#define DD 2048
#define HH 16
#define HDD 128
#define MROWS (BB*TT)   // 4096

// ---------------- scratch (static device globals; no runtime alloc) ----------------
__device__ float g_qkv[(size_t)BB * TT * 3 * DD];   // [B,T,3D]

// bf16 hi/lo splits
__device__ __nv_bfloat16 g_xhi[(size_t)MROWS * DD];
__device__ __nv_bfloat16 g_xlo[(size_t)MROWS * DD];
__device__ __nv_bfloat16 g_wqh[(size_t)3 * DD * DD];
__device__ __nv_bfloat16 g_wql[(size_t)3 * DD * DD];
__device__ __nv_bfloat16 g_woh[(size_t)DD * DD];
__device__ __nv_bfloat16 g_wol[(size_t)DD * DD];
__device__ __nv_bfloat16 g_ahi[(size_t)MROWS * DD];   // attn out (written by flash)
__device__ __nv_bfloat16 g_alo[(size_t)MROWS * DD];

// q/k/v hi-lo bf16, [B,H,T,HD]
#define QKVN ((size_t)BB * HH * TT * HDD)
__device__ __nv_bfloat16 g_qh[QKVN];
__device__ __nv_bfloat16 g_ql[QKVN];
__device__ __nv_bfloat16 g_kh[QKVN];
__device__ __nv_bfloat16 g_kl[QKVN];
__device__ __nv_bfloat16 g_vh[QKVN];
__device__ __nv_bfloat16 g_vl[QKVN];

// ---------------- PTX helpers (sm_80-era, safe on plain sm_100) ----------------
__device__ __forceinline__ uint32_t smem_u32(const void* p) {
    uint32_t a;
    asm("{ .reg .u64 t; cvta.to.shared.u64 t, %1; cvt.u32.u64 %0, t; }" : "=r"(a) : "l"(p));
    return a;
}
#define CP_ASYNC16(dst, src) \
    asm volatile("cp.async.cg.shared.global [%0], [%1], 16;" :: "r"(dst), "l"(src))
#define CP_COMMIT() asm volatile("cp.async.commit_group;" ::: "memory")
#define CP_WAIT0()  asm volatile("cp.async.wait_group 0;" ::: "memory")
#define CP_WAIT1()  asm volatile("cp.async.wait_group 1;" ::: "memory")

__device__ __forceinline__ void ldmx4(uint32_t* r, uint32_t addr) {
    asm volatile("ldmatrix.sync.aligned.m8n8.x4.shared.b16 {%0,%1,%2,%3}, [%4];"
                 : "=r"(r[0]), "=r"(r[1]), "=r"(r[2]), "=r"(r[3]) : "r"(addr));
}
__device__ __forceinline__ void ldmx4t(uint32_t* r, uint32_t addr) {
    asm volatile("ldmatrix.sync.aligned.m8n8.x4.trans.shared.b16 {%0,%1,%2,%3}, [%4];"
                 : "=r"(r[0]), "=r"(r[1]), "=r"(r[2]), "=r"(r[3]) : "r"(addr));
}
__device__ __forceinline__ void mma_bf16(float* d, const uint32_t* a, const uint32_t* b) {
    asm volatile(
        "mma.sync.aligned.m16n8k16.row.col.f32.bf16.bf16.f32 "
        "{%0,%1,%2,%3}, {%4,%5,%6,%7}, {%8,%9}, {%0,%1,%2,%3};"
        : "+f"(d[0]), "+f"(d[1]), "+f"(d[2]), "+f"(d[3])
        : "r"(a[0]), "r"(a[1]), "r"(a[2]), "r"(a[3]), "r"(b[0]), "r"(b[1]));
}
// pack fp32 pair (p0 -> low, p1 -> high) into bf16x2 hi part + residual lo part
__device__ __forceinline__ void pack_hilo(float p0, float p1, uint32_t& hp, uint32_t& lp) {
    asm("cvt.rn.bf16x2.f32 %0, %1, %2;" : "=r"(hp) : "f"(p1), "f"(p0));
    float h0 = __uint_as_float(hp << 16);
    float h1 = __uint_as_float(hp & 0xFFFF0000u);
    float l0 = p0 - h0, l1 = p1 - h1;
    asm("cvt.rn.bf16x2.f32 %0, %1, %2;" : "=r"(lp) : "f"(l1), "f"(l0));
}

// ---------------- fused fp32 -> bf16 hi/lo split for x, Wqkv, Wout ----------------
__global__ void split3_bf16(const float* __restrict__ x,
                            const float* __restrict__ wq,
                            const float* __restrict__ wo,
                            __nv_bfloat16* __restrict__ xhi, __nv_bfloat16* __restrict__ xlo,
                            __nv_bfloat16* __restrict__ wqh, __nv_bfloat16* __restrict__ wql,
                            __nv_bfloat16* __restrict__ woh, __nv_bfloat16* __restrict__ wol)
{
    const int n_x = MROWS * DD / 4;          // 2,097,152
    const int n_q = 3 * DD * DD / 4;         // 3,145,728
    const int n_o = DD * DD / 4;             // 1,048,576
    int i = blockIdx.x * 256 + threadIdx.x;
    const float* s; __nv_bfloat16 *hi, *lo;
    if (i < n_x) { s = x; hi = xhi; lo = xlo; }
    else if (i < n_x + n_q) { i -= n_x; s = wq; hi = wqh; lo = wql; }
    else {
        i -= n_x + n_q;
        if (i >= n_o) return;
        s = wo; hi = woh; lo = wol;
    }
    float4 v = ((const float4*)s)[i];
    __nv_bfloat16 h0 = __float2bfloat16(v.x), h1 = __float2bfloat16(v.y);
    __nv_bfloat16 h2 = __float2bfloat16(v.z), h3 = __float2bfloat16(v.w);
    __nv_bfloat16 l0 = __float2bfloat16(v.x - __bfloat162float(h0));
    __nv_bfloat16 l1 = __float2bfloat16(v.y - __bfloat162float(h1));
    __nv_bfloat16 l2 = __float2bfloat16(v.z - __bfloat162float(h2));
    __nv_bfloat16 l3 = __float2bfloat16(v.w - __bfloat162float(h3));
    __nv_bfloat162* hp = (__nv_bfloat162*)hi;
    __nv_bfloat162* lp = (__nv_bfloat162*)lo;
    hp[2 * i]     = __nv_bfloat162(h0, h1);
    hp[2 * i + 1] = __nv_bfloat162(h2, h3);
    lp[2 * i]     = __nv_bfloat162(l0, l1);
    lp[2 * i + 1] = __nv_bfloat162(l2, l3);
}

// ---------------- mma.sync bf16-split GEMM: C[M,N] = A[M,K] @ B[N,K]^T ----------------
#define GK 32
#define SROWB 80
#define TBYTES (128 * SROWB)
#define GEMM_SMEM (8 * TBYTES)         // 81920

__global__ __launch_bounds__(256, 2) void gemm_bf16s(
    const __nv_bfloat16* __restrict__ Ah, const __nv_bfloat16* __restrict__ Al,
    const __nv_bfloat16* __restrict__ Bh, const __nv_bfloat16* __restrict__ Bl,
    float* __restrict__ C, int M, int N, int K)
{
    extern __shared__ char smg[];
    const uint32_t sb = smem_u32(smg);
    const int tid = threadIdx.x;
    const int wid = tid >> 5, lane = tid & 31;
    const int wm = wid >> 2, wn = wid & 3;
    const int brow = blockIdx.y * 128, bcol = blockIdx.x * 128;
    const int nch = K / GK;

    const __nv_bfloat16* srcs[4] = { Ah, Al, Bh, Bl };

    auto load_chunk = [&](int c) {
        const uint32_t base = sb + (uint32_t)(c & 1) * 4 * TBYTES;
        const size_t ka = (size_t)c * GK;
        #pragma unroll
        for (int t = 0; t < 4; t++) {
            const __nv_bfloat16* s = srcs[t];
            const int rowbase = (t < 2) ? brow : bcol;
            #pragma unroll
            for (int j = 0; j < 2; j++) {
                int i = tid * 2 + j;
                int r = i >> 2, ch = i & 3;
                const __nv_bfloat16* g = s + (size_t)(rowbase + r) * K + ka + ch * 8;
                CP_ASYNC16(base + t * TBYTES + r * SROWB + ch * 16, g);
            }
        }
        CP_COMMIT();
    };

    float acc[4][4][4];
    #pragma unroll
    for (int mt = 0; mt < 4; mt++)
        #pragma unroll
        for (int nt = 0; nt < 4; nt++)
            #pragma unroll
            for (int e = 0; e < 4; e++) acc[mt][nt][e] = 0.f;

    const uint32_t a_row = (uint32_t)(wm * 64 + (lane & 15)) * SROWB + (lane >> 4) * 16;
    const uint32_t b_row0 = (uint32_t)(wn * 32 + ((lane >> 4) & 1) * 8 + (lane & 7)) * SROWB
                            + ((lane >> 3) & 1) * 16;

    load_chunk(0);

    for (int c = 0; c < nch; c++) {
        if (c + 1 < nch) { load_chunk(c + 1); CP_WAIT1(); }
        else CP_WAIT0();
        __syncthreads();

        const uint32_t bufb = sb + (uint32_t)(c & 1) * 4 * TBYTES;
        #pragma unroll
        for (int ks = 0; ks < 2; ks++) {
            const uint32_t ko = ks * 32;
            uint32_t ah[4][4], al[4][4];
            #pragma unroll
            for (int mt = 0; mt < 4; mt++) {
                uint32_t addr = bufb + a_row + (uint32_t)(mt * 16) * SROWB + ko;
                ldmx4(ah[mt], addr);
                ldmx4(al[mt], addr + TBYTES);
            }
            uint32_t bh[4][2], bl[4][2];
            #pragma unroll
            for (int p = 0; p < 2; p++) {
                uint32_t addr = bufb + 2 * TBYTES + b_row0 + (uint32_t)(p * 16) * SROWB + ko;
                uint32_t rh[4], rl[4];
                ldmx4(rh, addr);
                ldmx4(rl, addr + TBYTES);
                bh[2*p][0] = rh[0]; bh[2*p][1] = rh[1];
                bh[2*p+1][0] = rh[2]; bh[2*p+1][1] = rh[3];
                bl[2*p][0] = rl[0]; bl[2*p][1] = rl[1];
                bl[2*p+1][0] = rl[2]; bl[2*p+1][1] = rl[3];
            }
            #pragma unroll
            for (int mt = 0; mt < 4; mt++)
                #pragma unroll
                for (int nt = 0; nt < 4; nt++) {
                    mma_bf16(acc[mt][nt], ah[mt], bh[nt]);
                    mma_bf16(acc[mt][nt], ah[mt], bl[nt]);
                    mma_bf16(acc[mt][nt], al[mt], bh[nt]);
                }
        }
        __syncthreads();
    }

    const int g = lane >> 2, t4 = lane & 3;
    #pragma unroll
    for (int mt = 0; mt < 4; mt++) {
        #pragma unroll
        for (int nt = 0; nt < 4; nt++) {
            int row = brow + wm * 64 + mt * 16 + g;
            int col = bcol + wn * 32 + nt * 8 + 2 * t4;
            float* p0 = C + (size_t)row * N + col;
            float* p1 = C + (size_t)(row + 8) * N + col;
            p0[0] = acc[mt][nt][0]; p0[1] = acc[mt][nt][1];
            p1[0] = acc[mt][nt][2]; p1[1] = acc[mt][nt][3];
        }
    }
}

// ---------------- RoPE + split into bf16 hi/lo [B,H,T,HD]; q pre-scaled ----------------
// q scale = (1/sqrt(128)) * log2(e)  -> softmax runs in base 2
__global__ void rope_split(const float* __restrict__ qkv,
                           const float* __restrict__ cosT,
                           const float* __restrict__ sinT)
{
    const int idx = blockIdx.x;
    const int h = idx % HH;
    const int t = (idx / HH) % TT;
    const int b = idx / (HH * TT);
    const int c = threadIdx.x;

    const size_t ibase = ((size_t)(b * TT + t)) * (3 * DD) + h * HDD;
    float qv = qkv[ibase + c];
    float kv = qkv[ibase + DD + c];
    float vv = qkv[ibase + 2 * DD + c];
    float qp = qkv[ibase + (c ^ 64)];
    float kp = qkv[ibase + DD + (c ^ 64)];
    float cs = cosT[t * HDD + c];
    float sn = sinT[t * HDD + c];
    float sgn = (c < 64) ? -1.f : 1.f;

    float q = fmaf(qv, cs, sgn * qp * sn) * 0.12751744509597396f;  // 1/sqrt(128) * log2(e)
    float k = fmaf(kv, cs, sgn * kp * sn);

    const size_t o = (((size_t)(b * HH + h)) * TT + t) * HDD + c;
    __nv_bfloat16 qh = __float2bfloat16(q);
    __nv_bfloat16 kh = __float2bfloat16(k);
    __nv_bfloat16 vh = __float2bfloat16(vv);
    g_qh[o] = qh; g_ql[o] = __float2bfloat16(q - __bfloat162float(qh));
    g_kh[o] = kh; g_kl[o] = __float2bfloat16(k - __bfloat162float(kh));
    g_vh[o] = vh; g_vl[o] = __float2bfloat16(vv - __bfloat162float(vh));
}

// ---------------- tensor-core flash attention (R7 structure + Q-hi reg hoist + exp2) --
#define FQ2 128
#define FK2 64
#define FSTR 272                        // row stride bytes (128 bf16 + 16B pad)
#define SM_QH 0
#define SM_QL (FQ2*FSTR)                // 34816
#define SM_K  (2*FQ2*FSTR)              // 69632 ; + buf*34816 ; lo at +17408
#define SM_V  (SM_K + 2*2*FK2*FSTR)     // 139264 ; same layout
#define KVBUF (2*FK2*FSTR)              // 34816 per buffer (hi+lo)
#define HLOFF (FK2*FSTR)                // 17408 hi->lo offset
#define FLASH2_SMEM (SM_V + 2*KVBUF)    // 208896

__global__ __launch_bounds__(256, 1) void flash_mma()
{
    extern __shared__ char smf[];
    const uint32_t sb = smem_u32(smf);
    const int tid = threadIdx.x;
    const int wid = tid >> 5, lane = tid & 31;

    // longest-first static schedule: linear index -> (qt desc, h, b)
    const int l = blockIdx.x + 16 * blockIdx.y + 256 * blockIdx.z;   // 0..511
    const int qt = (TT / FQ2 - 1) - (l >> 5);                        // 15..0
    const int bh = l & 31;
    const int h = bh & 15, b = bh >> 4;

    const size_t hb = ((size_t)(b * HH + h)) * TT * HDD;
    const size_t qb = hb + (size_t)qt * FQ2 * HDD;

    auto load_kv = [&](int kt) {
        const uint32_t kbase = sb + SM_K + (uint32_t)(kt & 1) * KVBUF;
        const uint32_t vbase = sb + SM_V + (uint32_t)(kt & 1) * KVBUF;
        const size_t kb = hb + (size_t)kt * FK2 * HDD;
        #pragma unroll
        for (int j = 0; j < 4; j++) {
            int i = tid + j * 256;              // 0..1023
            int r = i >> 4, ch = i & 15;
            size_t goff = kb + (size_t)r * HDD + ch * 8;
            uint32_t soff = (uint32_t)r * FSTR + ch * 16;
            CP_ASYNC16(kbase + soff, g_kh + goff);
            CP_ASYNC16(kbase + HLOFF + soff, g_kl + goff);
            CP_ASYNC16(vbase + soff, g_vh + goff);
            CP_ASYNC16(vbase + HLOFF + soff, g_vl + goff);
        }
        CP_COMMIT();
    };

    // ---- prologue: Q hi/lo via cp.async (resident), then first K/V tile ----
    #pragma unroll
    for (int j = 0; j < 8; j++) {
        int i = tid + j * 256;                  // 0..2047
        int r = i >> 4, ch = i & 15;
        size_t goff = qb + (size_t)r * HDD + ch * 8;
        uint32_t soff = (uint32_t)r * FSTR + ch * 16;
        CP_ASYNC16(sb + SM_QH + soff, g_qh + goff);
        CP_ASYNC16(sb + SM_QL + soff, g_ql + goff);
    }
    CP_COMMIT();
    load_kv(0);

    // fragment base addresses
    const uint32_t aq  = sb + SM_QH + (uint32_t)(wid * 16 + (lane & 15)) * FSTR + (lane >> 4) * 16;
    const uint32_t akr = (uint32_t)((lane & 7) + ((lane >> 4) << 3)) * FSTR + ((lane >> 3) & 1) * 16;
    const uint32_t avr = (uint32_t)((lane & 7) + ((lane >> 3) & 1) * 8) * FSTR + ((lane >> 4) << 3) * 2;

    // ---- hoist Q-hi fragments into registers (invariant across kt) ----
    CP_WAIT1();            // Q group complete (kv0 may still be in flight)
    __syncthreads();
    uint32_t qhf[8][4];
    #pragma unroll
    for (int ks = 0; ks < 8; ks++)
        ldmx4(qhf[ks], aq + ks * 32);

    float oacc[16][4];
    #pragma unroll
    for (int i = 0; i < 16; i++)
        #pragma unroll
        for (int e = 0; e < 4; e++) oacc[i][e] = 0.f;
    float mrow[2] = { -1e30f, -1e30f }, lrow[2] = { 0.f, 0.f };

    const int ktmax = 2 * qt + 1;
    for (int kt = 0; kt <= ktmax; kt++) {
        if (kt < ktmax) { load_kv(kt + 1); CP_WAIT1(); }
        else CP_WAIT0();
        __syncthreads();

        const uint32_t kbase = sb + SM_K + (uint32_t)(kt & 1) * KVBUF;
        const uint32_t vbase = sb + SM_V + (uint32_t)(kt & 1) * KVBUF;

        // ---- S = Q @ K^T (scale+log2e folded into Q) ----
        float sacc[8][4];
        #pragma unroll
        for (int nt = 0; nt < 8; nt++)
            #pragma unroll
            for (int e = 0; e < 4; e++) sacc[nt][e] = 0.f;

        #pragma unroll
        for (int ks = 0; ks < 8; ks++) {
            uint32_t ql4[4];
            ldmx4(ql4, aq + (SM_QL - SM_QH) + ks * 32);
            #pragma unroll
            for (int p = 0; p < 4; p++) {
                uint32_t kh4[4], kl4[4];
                uint32_t kaddr = kbase + akr + (uint32_t)(p * 16) * FSTR + ks * 32;
                ldmx4(kh4, kaddr);
                ldmx4(kl4, kaddr + HLOFF);
                mma_bf16(sacc[2*p],   qhf[ks], &kh4[0]);
                mma_bf16(sacc[2*p],   qhf[ks], &kl4[0]);
                mma_bf16(sacc[2*p],   ql4,     &kh4[0]);
                mma_bf16(sacc[2*p+1], qhf[ks], &kh4[2]);
                mma_bf16(sacc[2*p+1], qhf[ks], &kl4[2]);
                mma_bf16(sacc[2*p+1], ql4,     &kh4[2]);
            }
        }

        // ---- causal mask (only diagonal-adjacent tiles) ----
        if (kt >= 2 * qt) {
            const int qrow0 = qt * FQ2 + wid * 16 + (lane >> 2);
            #pragma unroll
            for (int nt = 0; nt < 8; nt++) {
                int kc = kt * FK2 + nt * 8 + 2 * (lane & 3);
                if (kc     > qrow0)     sacc[nt][0] = -1e30f;
                if (kc + 1 > qrow0)     sacc[nt][1] = -1e30f;
                if (kc     > qrow0 + 8) sacc[nt][2] = -1e30f;
                if (kc + 1 > qrow0 + 8) sacc[nt][3] = -1e30f;
            }
        }

        // ---- online softmax, base 2 (rows g, g+8; 4-lane groups share a row) ----
        #pragma unroll
        for (int r = 0; r < 2; r++) {
            float mt = -1e30f;
            #pragma unroll
            for (int nt = 0; nt < 8; nt++)
                mt = fmaxf(mt, fmaxf(sacc[nt][2 * r], sacc[nt][2 * r + 1]));
            mt = fmaxf(mt, __shfl_xor_sync(0xffffffffu, mt, 1));
            mt = fmaxf(mt, __shfl_xor_sync(0xffffffffu, mt, 2));
            float mnew = fmaxf(mrow[r], mt);
            float alpha = exp2f(mrow[r] - mnew);
            mrow[r] = mnew;
            float rs = 0.f;
            #pragma unroll
            for (int nt = 0; nt < 8; nt++) {
                float p0 = exp2f(sacc[nt][2 * r]     - mnew);
                float p1 = exp2f(sacc[nt][2 * r + 1] - mnew);
                sacc[nt][2 * r] = p0; sacc[nt][2 * r + 1] = p1;
                rs += p0 + p1;
            }
            rs += __shfl_xor_sync(0xffffffffu, rs, 1);
            rs += __shfl_xor_sync(0xffffffffu, rs, 2);
            lrow[r] = lrow[r] * alpha + rs;
            #pragma unroll
            for (int nt2 = 0; nt2 < 16; nt2++) {
                oacc[nt2][2 * r]     *= alpha;
                oacc[nt2][2 * r + 1] *= alpha;
            }
        }

        // ---- pack P into bf16 hi/lo A-fragments ----
        uint32_t ph[4][4], pl[4][4];
        #pragma unroll
        for (int ks2 = 0; ks2 < 4; ks2++) {
            pack_hilo(sacc[2*ks2][0],   sacc[2*ks2][1],   ph[ks2][0], pl[ks2][0]);
            pack_hilo(sacc[2*ks2][2],   sacc[2*ks2][3],   ph[ks2][1], pl[ks2][1]);
            pack_hilo(sacc[2*ks2+1][0], sacc[2*ks2+1][1], ph[ks2][2], pl[ks2][2]);
            pack_hilo(sacc[2*ks2+1][2], sacc[2*ks2+1][3], ph[ks2][3], pl[ks2][3]);
        }

        // ---- O += P @ V (V fragments via ldmatrix.trans, row-major V) ----
        #pragma unroll
        for (int ks2 = 0; ks2 < 4; ks2++) {
            #pragma unroll
            for (int np = 0; np < 8; np++) {
                uint32_t vh4[4], vl4[4];
                uint32_t vaddr = vbase + avr + (uint32_t)(ks2 * 16) * FSTR + (np * 16) * 2;
                ldmx4t(vh4, vaddr);
                ldmx4t(vl4, vaddr + HLOFF);
                mma_bf16(oacc[2*np],   ph[ks2], &vh4[0]);
                mma_bf16(oacc[2*np],   ph[ks2], &vl4[0]);
                mma_bf16(oacc[2*np],   pl[ks2], &vh4[0]);
                mma_bf16(oacc[2*np+1], ph[ks2], &vh4[2]);
                mma_bf16(oacc[2*np+1], ph[ks2], &vl4[2]);
                mma_bf16(oacc[2*np+1], pl[ks2], &vh4[2]);
            }
        }
        __syncthreads();
    }

    // ---- epilogue: normalize and write bf16 hi/lo out-proj input [B,T,D] ----
    const float inv0 = 1.f / lrow[0], inv1 = 1.f / lrow[1];
    const int row0 = qt * FQ2 + wid * 16 + (lane >> 2);
    #pragma unroll
    for (int nt2 = 0; nt2 < 16; nt2++) {
        int col = h * HDD + nt2 * 8 + 2 * (lane & 3);
        size_t i0 = (size_t)(b * TT + row0) * DD + col;
        size_t i1 = (size_t)(b * TT + row0 + 8) * DD + col;
        uint32_t hp, lp;
        pack_hilo(oacc[nt2][0] * inv0, oacc[nt2][1] * inv0, hp, lp);
        *(uint32_t*)&g_ahi[i0] = hp; *(uint32_t*)&g_alo[i0] = lp;
        pack_hilo(oacc[nt2][2] * inv1, oacc[nt2][3] * inv1, hp, lp);
        *(uint32_t*)&g_ahi[i1] = hp; *(uint32_t*)&g_alo[i1] = lp;
    }
}

// ---------------- launch ----------------
extern "C" void kernel_launch(void* const* d_in, const int* in_sizes, int n_in,
                              void* d_out, int out_size)
{
    const float* x    = (const float*)d_in[0];
    const float* cosT = (const float*)d_in[1];
    const float* sinT = (const float*)d_in[2];
    const float* Wqkv = (const float*)d_in[3];
    const float* Wout = (const float*)d_in[4];
    float* out = (float*)d_out;

    float* qkv_p;
    cudaGetSymbolAddress((void**)&qkv_p, g_qkv);
    __nv_bfloat16 *xhi, *xlo, *wqh, *wql, *woh, *wol, *ahi, *alo;
    cudaGetSymbolAddress((void**)&xhi, g_xhi);
    cudaGetSymbolAddress((void**)&xlo, g_xlo);
    cudaGetSymbolAddress((void**)&wqh, g_wqh);
    cudaGetSymbolAddress((void**)&wql, g_wql);
    cudaGetSymbolAddress((void**)&woh, g_woh);
    cudaGetSymbolAddress((void**)&wol, g_wol);
    cudaGetSymbolAddress((void**)&ahi, g_ahi);
    cudaGetSymbolAddress((void**)&alo, g_alo);

    cudaFuncSetAttribute(gemm_bf16s, cudaFuncAttributeMaxDynamicSharedMemorySize, GEMM_SMEM);
    cudaFuncSetAttribute(flash_mma, cudaFuncAttributeMaxDynamicSharedMemorySize, FLASH2_SMEM);

    // 0) fused bf16 hi/lo splits of x, Wqkv, Wout
    {
        int total = MROWS * DD / 4 + 3 * DD * DD / 4 + DD * DD / 4;
        split3_bf16<<<(total + 255) / 256, 256>>>(x, Wqkv, Wout,
                                                  xhi, xlo, wqh, wql, woh, wol);
    }

    // 1) QKV projection (tensor cores)
    gemm_bf16s<<<dim3(3 * DD / 128, MROWS / 128), 256, GEMM_SMEM>>>(
        xhi, xlo, wqh, wql, qkv_p, MROWS, 3 * DD, DD);

    // 2) RoPE + bf16 hi/lo split of q,k,v (q pre-scaled by 1/sqrt(128)*log2e)
    rope_split<<<BB * TT * HH, HDD>>>(qkv_p, cosT, sinT);

    // 3) causal flash attention (tensor cores), writes g_ahi/g_alo
    flash_mma<<<dim3(TT / FQ2, HH, BB), 256, FLASH2_SMEM>>>();

    // 4) output projection (tensor cores)
    gemm_bf16s<<<dim3(DD / 128, MROWS / 128), 256, GEMM_SMEM>>>(
        ahi, alo, woh, wol, out, MROWS, DD, DD);
}